// round 1
// baseline (speedup 1.0000x reference)
#include <cuda_runtime.h>
#include <math.h>

#define T_DIM  2048
#define B_DIM  8
#define IN_D   512
#define DV     512
#define DK     128
#define CHK    128
#define NCH    16
#define EPSV   1e-8f

// ---------------- scratch (static device globals; no allocation) ----------------
__device__ float g_v  [T_DIM*B_DIM*DV];       // (t*B+b, d)
__device__ float g_k  [T_DIM*B_DIM*DK];       // raw k proj
__device__ float g_q  [T_DIM*B_DIM*DK];       // raw q proj
__device__ float g_a  [T_DIM*B_DIM*DK];       // raw alpha pre-sigmoid
__device__ float g_qt [NCH*B_DIM*CHK*DK];     // [c][b][t][n]  q * cp
__device__ float g_kt [NCH*B_DIM*CHK*DK];     // [c][b][t][n]  k / (cp+eps)
__device__ float g_cpl[NCH*B_DIM*DK];         // [c][b][n]     cp at t=C-1
__device__ float g_Am [NCH*B_DIM*CHK*CHK];    // [c][b][t][s]  causal-masked attention
__device__ float g_U  [NCH*B_DIM*DV*DK];      // [c][b][d][n]  V^T k~
__device__ float g_S  [NCH*B_DIM*DV*DK];      // [c][b][d][n]  state BEFORE chunk c

// ---------------- generic strided/batched fp32 GEMM ----------------
// C[m][n] (+)= sum_k A[m][k]*B[k][n]  (+ bias[n]) (causal mask: n>m -> 0)
// batch z decoded as (cz = z/nb, bb = z%nb); per-operand chunk/batch strides.
struct GemmArgs {
    const float* A; const float* B; float* C; const float* bias;
    int M, N, K, nb;
    long as_m, as_k, a_cs, a_bs;
    long bs_k, bs_n, b_cs, b_bs;
    long cs_m, c_cs, c_bs;
    int accum, causal;
};

#define BM 128
#define BN 128
#define BK 16

__global__ __launch_bounds__(256) void gemm_kernel(GemmArgs g) {
    __shared__ float As[BK][BM];
    __shared__ float Bs[BK][BN];

    int bz = blockIdx.z;
    int cz = bz / g.nb, bb = bz % g.nb;
    const float* Ap = g.A + cz * g.a_cs + bb * g.a_bs;
    const float* Bp = g.B + cz * g.b_cs + bb * g.b_bs;
    float*       Cp = g.C + cz * g.c_cs + bb * g.c_bs;

    int m0 = blockIdx.y * BM, n0 = blockIdx.x * BN;
    int tid = threadIdx.x;
    int tx = tid & 15, ty = tid >> 4;

    float acc[8][8];
#pragma unroll
    for (int i = 0; i < 8; i++)
#pragma unroll
        for (int j = 0; j < 8; j++) acc[i][j] = 0.f;

    for (int k0 = 0; k0 < g.K; k0 += BK) {
        // load A tile (coalesce along the unit-stride dim)
        if (g.as_k == 1) {
#pragma unroll
            for (int i = 0; i < (BM * BK) / 256; i++) {
                int idx = tid + i * 256;
                int k = idx & (BK - 1), m = idx / BK;
                As[k][m] = Ap[(long)(m0 + m) * g.as_m + (long)(k0 + k)];
            }
        } else {
#pragma unroll
            for (int i = 0; i < (BM * BK) / 256; i++) {
                int idx = tid + i * 256;
                int m = idx & (BM - 1), k = idx / BM;
                As[k][m] = Ap[(long)(m0 + m) * g.as_m + (long)(k0 + k) * g.as_k];
            }
        }
        // load B tile
        if (g.bs_k == 1) {
#pragma unroll
            for (int i = 0; i < (BN * BK) / 256; i++) {
                int idx = tid + i * 256;
                int k = idx & (BK - 1), n = idx / BK;
                Bs[k][n] = Bp[(long)(k0 + k) + (long)(n0 + n) * g.bs_n];
            }
        } else {
#pragma unroll
            for (int i = 0; i < (BN * BK) / 256; i++) {
                int idx = tid + i * 256;
                int n = idx & (BN - 1), k = idx / BN;
                Bs[k][n] = Bp[(long)(k0 + k) * g.bs_k + (long)(n0 + n) * g.bs_n];
            }
        }
        __syncthreads();

#pragma unroll
        for (int kk = 0; kk < BK; kk++) {
            float af[8], bf[8];
#pragma unroll
            for (int i = 0; i < 8; i++) af[i] = As[kk][ty + 16 * i];
#pragma unroll
            for (int j = 0; j < 8; j++) bf[j] = Bs[kk][tx + 16 * j];
#pragma unroll
            for (int i = 0; i < 8; i++)
#pragma unroll
                for (int j = 0; j < 8; j++)
                    acc[i][j] = fmaf(af[i], bf[j], acc[i][j]);
        }
        __syncthreads();
    }

#pragma unroll
    for (int i = 0; i < 8; i++) {
        int row = m0 + ty + 16 * i;
#pragma unroll
        for (int j = 0; j < 8; j++) {
            int col = n0 + tx + 16 * j;
            float v = acc[i][j];
            if (g.bias) v += g.bias[col];
            if (g.causal && col > row) v = 0.f;
            long idx = (long)row * g.cs_m + col;
            if (g.accum) Cp[idx] += v;
            else         Cp[idx] = v;
        }
    }
}

// ---------------- per-(chunk,batch) decay prep: cp, q~, k~ ----------------
__global__ void prep_kernel() {
    int c = blockIdx.x, b = blockIdx.y, n = threadIdx.x;   // n in [0,128)
    float cp = 1.f;
    long base_o = (((long)c * B_DIM + b) * CHK) * DK + n;
    for (int t = 0; t < CHK; t++) {
        long row = (long)(c * CHK + t) * B_DIM + b;
        float av = g_a[row * DK + n];
        float sg = 1.f / (1.f + expf(-av));
        cp *= fmaxf(sg, EPSV);
        g_qt[base_o + (long)t * DK] = g_q[row * DK + n] * cp;
        g_kt[base_o + (long)t * DK] = g_k[row * DK + n] / (cp + EPSV);
    }
    g_cpl[((long)c * B_DIM + b) * DK + n] = cp;
}

// ---------------- 16-step inter-chunk state scan (parallel over b,d,n) ----------------
__global__ void scan_kernel() {
    int id = blockIdx.x * blockDim.x + threadIdx.x;   // over B*DV*DK = 524288
    int n = id & (DK - 1);
    int d = (id >> 7) & (DV - 1);
    int b = id >> 16;
    float s = 0.f;
#pragma unroll
    for (int c = 0; c < NCH; c++) {
        long off = (((long)c * B_DIM + b) * DV + d) * DK + n;
        g_S[off] = s;                                   // state BEFORE chunk c
        float cl = g_cpl[((long)c * B_DIM + b) * DK + n];
        s = cl * (s + g_U[off]);
    }
}

// ---------------- host launcher ----------------
extern "C" void kernel_launch(void* const* d_in, const int* in_sizes, int n_in,
                              void* d_out, int out_size) {
    const float* x  = (const float*)d_in[0];
    const float* Wv = (const float*)d_in[1];
    const float* bv = (const float*)d_in[2];
    const float* Wk = (const float*)d_in[3];
    const float* bk = (const float*)d_in[4];
    const float* Wq = (const float*)d_in[5];
    const float* bq = (const float*)d_in[6];
    const float* Wa = (const float*)d_in[7];
    const float* ba = (const float*)d_in[8];
    float* y = (float*)d_out;

    float *pv, *pk, *pq, *pa, *pqt, *pkt, *pcpl, *pA, *pU, *pS;
    cudaGetSymbolAddress((void**)&pv,  g_v);
    cudaGetSymbolAddress((void**)&pk,  g_k);
    cudaGetSymbolAddress((void**)&pq,  g_q);
    cudaGetSymbolAddress((void**)&pa,  g_a);
    cudaGetSymbolAddress((void**)&pqt, g_qt);
    cudaGetSymbolAddress((void**)&pkt, g_kt);
    cudaGetSymbolAddress((void**)&pcpl,g_cpl);
    cudaGetSymbolAddress((void**)&pA,  g_Am);
    cudaGetSymbolAddress((void**)&pU,  g_U);
    cudaGetSymbolAddress((void**)&pS,  g_S);
    (void)pcpl; (void)in_sizes; (void)n_in; (void)out_size;

    const int M = T_DIM * B_DIM;  // 16384

    // ---- projections: C = X @ W^T + b ----
    GemmArgs ga = {};
    ga.A = x;  ga.as_m = IN_D; ga.as_k = 1; ga.a_cs = 0; ga.a_bs = 0;
    ga.bs_k = 1; ga.bs_n = IN_D; ga.b_cs = 0; ga.b_bs = 0;
    ga.c_cs = 0; ga.c_bs = 0; ga.nb = 1; ga.accum = 0; ga.causal = 0;
    ga.M = M; ga.K = IN_D;

    // v
    ga.B = Wv; ga.bias = bv; ga.C = pv; ga.N = DV; ga.cs_m = DV;
    gemm_kernel<<<dim3(DV / BN, M / BM, 1), 256>>>(ga);
    // k
    ga.B = Wk; ga.bias = bk; ga.C = pk; ga.N = DK; ga.cs_m = DK;
    gemm_kernel<<<dim3(1, M / BM, 1), 256>>>(ga);
    // q
    ga.B = Wq; ga.bias = bq; ga.C = pq;
    gemm_kernel<<<dim3(1, M / BM, 1), 256>>>(ga);
    // alpha (raw; sigmoid in prep)
    ga.B = Wa; ga.bias = ba; ga.C = pa;
    gemm_kernel<<<dim3(1, M / BM, 1), 256>>>(ga);

    // ---- decay prep ----
    prep_kernel<<<dim3(NCH, B_DIM), DK>>>();

    // ---- A = q~ @ k~^T, causal masked (per c,b) ----
    GemmArgs g3 = {};
    g3.A = pqt; g3.as_m = DK; g3.as_k = 1; g3.a_cs = (long)B_DIM*CHK*DK; g3.a_bs = (long)CHK*DK;
    g3.B = pkt; g3.bs_k = 1;  g3.bs_n = DK; g3.b_cs = (long)B_DIM*CHK*DK; g3.b_bs = (long)CHK*DK;
    g3.C = pA;  g3.cs_m = CHK; g3.c_cs = (long)B_DIM*CHK*CHK; g3.c_bs = (long)CHK*CHK;
    g3.bias = 0; g3.M = CHK; g3.N = CHK; g3.K = DK; g3.nb = B_DIM; g3.accum = 0; g3.causal = 1;
    gemm_kernel<<<dim3(1, 1, NCH * B_DIM), 256>>>(g3);

    // ---- y_intra = A @ V  -> d_out ----
    GemmArgs g4 = {};
    g4.A = pA; g4.as_m = CHK; g4.as_k = 1; g4.a_cs = (long)B_DIM*CHK*CHK; g4.a_bs = (long)CHK*CHK;
    g4.B = pv; g4.bs_k = (long)B_DIM*DV; g4.bs_n = 1; g4.b_cs = (long)CHK*B_DIM*DV; g4.b_bs = DV;
    g4.C = y;  g4.cs_m = (long)B_DIM*DV; g4.c_cs = (long)CHK*B_DIM*DV; g4.c_bs = DV;
    g4.bias = 0; g4.M = CHK; g4.N = DV; g4.K = CHK; g4.nb = B_DIM; g4.accum = 0; g4.causal = 0;
    gemm_kernel<<<dim3(DV / BN, 1, NCH * B_DIM), 256>>>(g4);

    // ---- U = V^T @ k~  (per c,b) ----
    GemmArgs g5 = {};
    g5.A = pv;  g5.as_m = 1; g5.as_k = (long)B_DIM*DV; g5.a_cs = (long)CHK*B_DIM*DV; g5.a_bs = DV;
    g5.B = pkt; g5.bs_k = DK; g5.bs_n = 1; g5.b_cs = (long)B_DIM*CHK*DK; g5.b_bs = (long)CHK*DK;
    g5.C = pU;  g5.cs_m = DK; g5.c_cs = (long)B_DIM*DV*DK; g5.c_bs = (long)DV*DK;
    g5.bias = 0; g5.M = DV; g5.N = DK; g5.K = CHK; g5.nb = B_DIM; g5.accum = 0; g5.causal = 0;
    gemm_kernel<<<dim3(1, DV / BM, NCH * B_DIM), 256>>>(g5);

    // ---- inter-chunk state scan ----
    scan_kernel<<<(B_DIM * DV * DK) / 256, 256>>>();

    // ---- y += q~ @ S_prev^T ----
    GemmArgs g7 = {};
    g7.A = pqt; g7.as_m = DK; g7.as_k = 1; g7.a_cs = (long)B_DIM*CHK*DK; g7.a_bs = (long)CHK*DK;
    g7.B = pS;  g7.bs_k = 1;  g7.bs_n = DK; g7.b_cs = (long)B_DIM*DV*DK; g7.b_bs = (long)DV*DK;
    g7.C = y;   g7.cs_m = (long)B_DIM*DV; g7.c_cs = (long)CHK*B_DIM*DV; g7.c_bs = DV;
    g7.bias = 0; g7.M = CHK; g7.N = DV; g7.K = DK; g7.nb = B_DIM; g7.accum = 1; g7.causal = 0;
    gemm_kernel<<<dim3(DV / BN, 1, NCH * B_DIM), 256>>>(g7);
}

// round 2
// speedup vs baseline: 1.8443x; 1.8443x over previous
#include <cuda_runtime.h>
#include <math.h>
#include <stdint.h>

#define T_DIM  2048
#define B_DIM  8
#define IN_D   512
#define DV     512
#define DK     128
#define CHK    128
#define NCH    16
#define EPSV   1e-8f

// ---------------- scratch (static device globals; no allocation) ----------------
__device__ float g_v  [T_DIM*B_DIM*DV];       // (t*B+b, d)
__device__ float g_k  [T_DIM*B_DIM*DK];
__device__ float g_q  [T_DIM*B_DIM*DK];
__device__ float g_a  [T_DIM*B_DIM*DK];
__device__ float g_qt [NCH*B_DIM*CHK*DK];     // [c][b][t][n]  q * cp
__device__ float g_kt [NCH*B_DIM*CHK*DK];     // [c][b][t][n]  k / (cp+eps)
__device__ float g_cpl[NCH*B_DIM*DK];         // [c][b][n]
__device__ float g_Am [NCH*B_DIM*CHK*CHK];    // [c][b][t][s]
__device__ float g_U  [NCH*B_DIM*DV*DK];      // [c][b][d][n]
__device__ float g_S  [NCH*B_DIM*DV*DK];      // [c][b][d][n]  state BEFORE chunk c

// ---------------- generic strided/batched tf32 tensor-core GEMM ----------------
struct GemmArgs {
    const float* A; const float* B; float* C; const float* bias;
    int M, N, K, nb;
    long as_m, as_k, a_cs, a_bs;
    long bs_k, bs_n, b_cs, b_bs;
    long cs_m, c_cs, c_bs;
    int accum, causal;
};

#define BM  128
#define BN  128
#define BKT 32
#define PAD 4

__device__ __forceinline__ uint32_t f2tf32(float f) {
    uint32_t u;
    asm("cvt.rna.tf32.f32 %0, %1;" : "=r"(u) : "f"(f));
    return u;
}

__device__ __forceinline__ void mma_tf32(float* d, const uint32_t* a, const uint32_t* b) {
    asm volatile(
        "mma.sync.aligned.m16n8k8.row.col.f32.tf32.tf32.f32 "
        "{%0,%1,%2,%3}, {%4,%5,%6,%7}, {%8,%9}, {%0,%1,%2,%3};"
        : "+f"(d[0]), "+f"(d[1]), "+f"(d[2]), "+f"(d[3])
        : "r"(a[0]), "r"(a[1]), "r"(a[2]), "r"(a[3]),
          "r"(b[0]), "r"(b[1]));
}

__global__ __launch_bounds__(256, 2) void gemm_tc(GemmArgs g) {
    __shared__ uint32_t As[BKT][BM + PAD];
    __shared__ uint32_t Bs[BKT][BN + PAD];

    int bz = blockIdx.z;
    int cz = bz / g.nb, bb = bz % g.nb;
    const float* Ap = g.A + cz * g.a_cs + bb * g.a_bs;
    const float* Bp = g.B + cz * g.b_cs + bb * g.b_bs;
    float*       Cp = g.C + cz * g.c_cs + bb * g.c_bs;

    int m0 = blockIdx.y * BM, n0 = blockIdx.x * BN;
    int tid = threadIdx.x;
    int warp = tid >> 5, lane = tid & 31;
    int wm0 = (warp & 1) * 64;       // 2 warp-rows of 64
    int wn0 = (warp >> 1) * 32;      // 4 warp-cols of 32
    int gid = lane >> 2, tig = lane & 3;

    float acc[4][4][4];
#pragma unroll
    for (int i = 0; i < 4; i++)
#pragma unroll
        for (int j = 0; j < 4; j++)
#pragma unroll
            for (int f = 0; f < 4; f++) acc[i][j][f] = 0.f;

    for (int k0 = 0; k0 < g.K; k0 += BKT) {
        // ---- load A tile (coalesce the unit-stride dim) ----
        if (g.as_k == 1) {
#pragma unroll
            for (int i = 0; i < (BM * BKT) / 256; i++) {
                int idx = tid + i * 256;
                int k = idx & (BKT - 1), m = idx >> 5;
                As[k][m] = f2tf32(Ap[(long)(m0 + m) * g.as_m + (k0 + k)]);
            }
        } else {
#pragma unroll
            for (int i = 0; i < (BM * BKT) / 256; i++) {
                int idx = tid + i * 256;
                int m = idx & (BM - 1), k = idx >> 7;
                As[k][m] = f2tf32(Ap[(long)(m0 + m) * g.as_m + (long)(k0 + k) * g.as_k]);
            }
        }
        // ---- load B tile ----
        if (g.bs_k == 1) {
#pragma unroll
            for (int i = 0; i < (BN * BKT) / 256; i++) {
                int idx = tid + i * 256;
                int k = idx & (BKT - 1), n = idx >> 5;
                Bs[k][n] = f2tf32(Bp[(long)(k0 + k) + (long)(n0 + n) * g.bs_n]);
            }
        } else {
#pragma unroll
            for (int i = 0; i < (BN * BKT) / 256; i++) {
                int idx = tid + i * 256;
                int n = idx & (BN - 1), k = idx >> 7;
                Bs[k][n] = f2tf32(Bp[(long)(k0 + k) * g.bs_k + (long)(n0 + n) * g.bs_n]);
            }
        }
        __syncthreads();

#pragma unroll
        for (int ks = 0; ks < BKT; ks += 8) {
            uint32_t af[4][4], bf2[4][2];
#pragma unroll
            for (int mi = 0; mi < 4; mi++) {
                int mr = wm0 + mi * 16 + gid;
                af[mi][0] = As[ks + tig][mr];
                af[mi][1] = As[ks + tig][mr + 8];
                af[mi][2] = As[ks + tig + 4][mr];
                af[mi][3] = As[ks + tig + 4][mr + 8];
            }
#pragma unroll
            for (int ni = 0; ni < 4; ni++) {
                int nc = wn0 + ni * 8 + gid;
                bf2[ni][0] = Bs[ks + tig][nc];
                bf2[ni][1] = Bs[ks + tig + 4][nc];
            }
#pragma unroll
            for (int mi = 0; mi < 4; mi++)
#pragma unroll
                for (int ni = 0; ni < 4; ni++)
                    mma_tf32(acc[mi][ni], af[mi], bf2[ni]);
        }
        __syncthreads();
    }

    // ---- epilogue ----
#pragma unroll
    for (int mi = 0; mi < 4; mi++) {
        int r0 = m0 + wm0 + mi * 16 + gid;
#pragma unroll
        for (int ni = 0; ni < 4; ni++) {
            int c0 = n0 + wn0 + ni * 8 + 2 * tig;
#pragma unroll
            for (int f = 0; f < 4; f++) {
                int row = r0 + (f >> 1) * 8;
                int col = c0 + (f & 1);
                float v = acc[mi][ni][f];
                if (g.bias) v += g.bias[col];
                if (g.causal && col > row) v = 0.f;
                long idx = (long)row * g.cs_m + col;
                if (g.accum) Cp[idx] += v;
                else         Cp[idx] = v;
            }
        }
    }
}

// ---------------- per-(chunk,batch) decay prep: cp, q~, k~ ----------------
__global__ void prep_kernel() {
    int c = blockIdx.x, b = blockIdx.y, n = threadIdx.x;
    float cp = 1.f;
    long base_o = (((long)c * B_DIM + b) * CHK) * DK + n;
    for (int t = 0; t < CHK; t++) {
        long row = (long)(c * CHK + t) * B_DIM + b;
        float av = g_a[row * DK + n];
        float sg = 1.f / (1.f + expf(-av));
        cp *= fmaxf(sg, EPSV);
        g_qt[base_o + (long)t * DK] = g_q[row * DK + n] * cp;
        g_kt[base_o + (long)t * DK] = g_k[row * DK + n] / (cp + EPSV);
    }
    g_cpl[((long)c * B_DIM + b) * DK + n] = cp;
}

// ---------------- 16-step inter-chunk state scan ----------------
__global__ void scan_kernel() {
    int id = blockIdx.x * blockDim.x + threadIdx.x;
    int n = id & (DK - 1);
    int d = (id >> 7) & (DV - 1);
    int b = id >> 16;
    float s = 0.f;
#pragma unroll
    for (int c = 0; c < NCH; c++) {
        long off = (((long)c * B_DIM + b) * DV + d) * DK + n;
        g_S[off] = s;
        float cl = g_cpl[((long)c * B_DIM + b) * DK + n];
        s = cl * (s + g_U[off]);
    }
}

// ---------------- host launcher ----------------
extern "C" void kernel_launch(void* const* d_in, const int* in_sizes, int n_in,
                              void* d_out, int out_size) {
    const float* x  = (const float*)d_in[0];
    const float* Wv = (const float*)d_in[1];
    const float* bv = (const float*)d_in[2];
    const float* Wk = (const float*)d_in[3];
    const float* bk = (const float*)d_in[4];
    const float* Wq = (const float*)d_in[5];
    const float* bq = (const float*)d_in[6];
    const float* Wa = (const float*)d_in[7];
    const float* ba = (const float*)d_in[8];
    float* y = (float*)d_out;

    float *pv, *pk, *pq, *pa, *pqt, *pkt, *pA, *pU, *pS;
    cudaGetSymbolAddress((void**)&pv,  g_v);
    cudaGetSymbolAddress((void**)&pk,  g_k);
    cudaGetSymbolAddress((void**)&pq,  g_q);
    cudaGetSymbolAddress((void**)&pa,  g_a);
    cudaGetSymbolAddress((void**)&pqt, g_qt);
    cudaGetSymbolAddress((void**)&pkt, g_kt);
    cudaGetSymbolAddress((void**)&pA,  g_Am);
    cudaGetSymbolAddress((void**)&pU,  g_U);
    cudaGetSymbolAddress((void**)&pS,  g_S);
    (void)in_sizes; (void)n_in; (void)out_size;

    const int M = T_DIM * B_DIM;  // 16384

    // ---- projections: C = X @ W^T + b ----
    GemmArgs ga = {};
    ga.A = x;  ga.as_m = IN_D; ga.as_k = 1; ga.a_cs = 0; ga.a_bs = 0;
    ga.bs_k = 1; ga.bs_n = IN_D; ga.b_cs = 0; ga.b_bs = 0;
    ga.c_cs = 0; ga.c_bs = 0; ga.nb = 1; ga.accum = 0; ga.causal = 0;
    ga.M = M; ga.K = IN_D;

    ga.B = Wv; ga.bias = bv; ga.C = pv; ga.N = DV; ga.cs_m = DV;
    gemm_tc<<<dim3(DV / BN, M / BM, 1), 256>>>(ga);
    ga.B = Wk; ga.bias = bk; ga.C = pk; ga.N = DK; ga.cs_m = DK;
    gemm_tc<<<dim3(1, M / BM, 1), 256>>>(ga);
    ga.B = Wq; ga.bias = bq; ga.C = pq;
    gemm_tc<<<dim3(1, M / BM, 1), 256>>>(ga);
    ga.B = Wa; ga.bias = ba; ga.C = pa;
    gemm_tc<<<dim3(1, M / BM, 1), 256>>>(ga);

    // ---- decay prep ----
    prep_kernel<<<dim3(NCH, B_DIM), DK>>>();

    // ---- A = q~ @ k~^T, causal masked (per c,b) ----
    GemmArgs g3 = {};
    g3.A = pqt; g3.as_m = DK; g3.as_k = 1; g3.a_cs = (long)B_DIM*CHK*DK; g3.a_bs = (long)CHK*DK;
    g3.B = pkt; g3.bs_k = 1;  g3.bs_n = DK; g3.b_cs = (long)B_DIM*CHK*DK; g3.b_bs = (long)CHK*DK;
    g3.C = pA;  g3.cs_m = CHK; g3.c_cs = (long)B_DIM*CHK*CHK; g3.c_bs = (long)CHK*CHK;
    g3.bias = 0; g3.M = CHK; g3.N = CHK; g3.K = DK; g3.nb = B_DIM; g3.accum = 0; g3.causal = 1;
    gemm_tc<<<dim3(1, 1, NCH * B_DIM), 256>>>(g3);

    // ---- y_intra = A @ V ----
    GemmArgs g4 = {};
    g4.A = pA; g4.as_m = CHK; g4.as_k = 1; g4.a_cs = (long)B_DIM*CHK*CHK; g4.a_bs = (long)CHK*CHK;
    g4.B = pv; g4.bs_k = (long)B_DIM*DV; g4.bs_n = 1; g4.b_cs = (long)CHK*B_DIM*DV; g4.b_bs = DV;
    g4.C = y;  g4.cs_m = (long)B_DIM*DV; g4.c_cs = (long)CHK*B_DIM*DV; g4.c_bs = DV;
    g4.bias = 0; g4.M = CHK; g4.N = DV; g4.K = CHK; g4.nb = B_DIM; g4.accum = 0; g4.causal = 0;
    gemm_tc<<<dim3(DV / BN, 1, NCH * B_DIM), 256>>>(g4);

    // ---- U = V^T @ k~ ----
    GemmArgs g5 = {};
    g5.A = pv;  g5.as_m = 1; g5.as_k = (long)B_DIM*DV; g5.a_cs = (long)CHK*B_DIM*DV; g5.a_bs = DV;
    g5.B = pkt; g5.bs_k = DK; g5.bs_n = 1; g5.b_cs = (long)B_DIM*CHK*DK; g5.b_bs = (long)CHK*DK;
    g5.C = pU;  g5.cs_m = DK; g5.c_cs = (long)B_DIM*DV*DK; g5.c_bs = (long)DV*DK;
    g5.bias = 0; g5.M = DV; g5.N = DK; g5.K = CHK; g5.nb = B_DIM; g5.accum = 0; g5.causal = 0;
    gemm_tc<<<dim3(1, DV / BM, NCH * B_DIM), 256>>>(g5);

    // ---- inter-chunk state scan ----
    scan_kernel<<<(B_DIM * DV * DK) / 256, 256>>>();

    // ---- y += q~ @ S_prev^T ----
    GemmArgs g7 = {};
    g7.A = pqt; g7.as_m = DK; g7.as_k = 1; g7.a_cs = (long)B_DIM*CHK*DK; g7.a_bs = (long)CHK*DK;
    g7.B = pS;  g7.bs_k = 1;  g7.bs_n = DK; g7.b_cs = (long)B_DIM*DV*DK; g7.b_bs = (long)DV*DK;
    g7.C = y;   g7.cs_m = (long)B_DIM*DV; g7.c_cs = (long)CHK*B_DIM*DV; g7.c_bs = DV;
    g7.bias = 0; g7.M = CHK; g7.N = DV; g7.K = DK; g7.nb = B_DIM; g7.accum = 1; g7.causal = 0;
    gemm_tc<<<dim3(DV / BN, 1, NCH * B_DIM), 256>>>(g7);
}

// round 3
// speedup vs baseline: 2.5362x; 1.3752x over previous
#include <cuda_runtime.h>
#include <math.h>
#include <stdint.h>

#define T_DIM  2048
#define B_DIM  8
#define IN_D   512
#define DV     512
#define DK     128
#define CHK    128
#define NCH    16
#define EPSV   1e-8f

#define BM  128
#define BN  128
#define BKT 16
#define PAD 4

// ---------------- scratch ----------------
__device__ float g_v  [T_DIM*B_DIM*DV];
__device__ float g_k  [T_DIM*B_DIM*DK];
__device__ float g_q  [T_DIM*B_DIM*DK];
__device__ float g_a  [T_DIM*B_DIM*DK];
__device__ float g_qt [NCH*B_DIM*CHK*DK];
__device__ float g_kt [NCH*B_DIM*CHK*DK];
__device__ float g_cpl[NCH*B_DIM*DK];
__device__ float g_Am [NCH*B_DIM*CHK*CHK];
__device__ float g_U  [NCH*B_DIM*DV*DK];
__device__ float g_S  [NCH*B_DIM*DV*DK];

struct GArgs {
    // op1
    const float *A1, *B1;
    long a1m, a1k, a1c, a1b, b1k, b1n, b1c, b1b;
    int K1;
    // op2 (fused second GEMM accumulating into same tile; A2==0 -> unused)
    const float *A2, *B2;
    long a2m, a2k, a2c, a2b, b2k, b2n, b2c, b2b;
    int K2;
    float* C; const float* bias;
    long cm, cc, cb;
    int nb, causal, multi;
    // multi-output projection mode (blockIdx.x selects entry)
    const float* Bm[7]; const float* biasm[7]; float* Cm[7];
    int noff[7]; long csm[7];
};

__device__ __forceinline__ uint32_t f2tf32(float f) {
    uint32_t u;
    asm("cvt.rna.tf32.f32 %0, %1;" : "=r"(u) : "f"(f));
    return u;
}

__device__ __forceinline__ void mma_tf32(float* d, const uint32_t* a, const uint32_t* b) {
    asm volatile(
        "mma.sync.aligned.m16n8k8.row.col.f32.tf32.tf32.f32 "
        "{%0,%1,%2,%3}, {%4,%5,%6,%7}, {%8,%9}, {%0,%1,%2,%3};"
        : "+f"(d[0]), "+f"(d[1]), "+f"(d[2]), "+f"(d[3])
        : "r"(a[0]), "r"(a[1]), "r"(a[2]), "r"(a[3]),
          "r"(b[0]), "r"(b[1]));
}

// double-buffered tf32 mainloop over one (A,B,K) operand pair
__device__ __forceinline__ void run_pipe(
    const float* Ap, long as_m, long as_k,
    const float* Bp, long bs_k, long bs_n,
    int K, int m0, int n0, int tid, int warp, int lane,
    float acc[4][4][4],
    uint32_t (&As)[2][BKT][BM + PAD],
    uint32_t (&Bs)[2][BKT][BN + PAD])
{
    int wm0 = (warp & 1) * 64;
    int wn0 = (warp >> 1) * 32;
    int gid = lane >> 2, tig = lane & 3;

    float ra[8], rb[8];

    auto load_regs = [&](int k0) {
        if (as_k == 1) {
#pragma unroll
            for (int i = 0; i < 8; i++) {
                int idx = tid + i * 256;
                int k = idx & 15, m = idx >> 4;
                ra[i] = Ap[(long)(m0 + m) * as_m + (k0 + k)];
            }
        } else {
#pragma unroll
            for (int i = 0; i < 8; i++) {
                int idx = tid + i * 256;
                int m = idx & 127, k = idx >> 7;
                ra[i] = Ap[(long)(m0 + m) * as_m + (long)(k0 + k) * as_k];
            }
        }
        if (bs_k == 1) {
#pragma unroll
            for (int i = 0; i < 8; i++) {
                int idx = tid + i * 256;
                int k = idx & 15, n = idx >> 4;
                rb[i] = Bp[(long)(k0 + k) + (long)(n0 + n) * bs_n];
            }
        } else {
#pragma unroll
            for (int i = 0; i < 8; i++) {
                int idx = tid + i * 256;
                int n = idx & 127, k = idx >> 7;
                rb[i] = Bp[(long)(k0 + k) * bs_k + (long)(n0 + n) * bs_n];
            }
        }
    };
    auto store_smem = [&](int buf) {
        if (as_k == 1) {
#pragma unroll
            for (int i = 0; i < 8; i++) {
                int idx = tid + i * 256;
                As[buf][idx & 15][idx >> 4] = f2tf32(ra[i]);
            }
        } else {
#pragma unroll
            for (int i = 0; i < 8; i++) {
                int idx = tid + i * 256;
                As[buf][idx >> 7][idx & 127] = f2tf32(ra[i]);
            }
        }
        if (bs_k == 1) {
#pragma unroll
            for (int i = 0; i < 8; i++) {
                int idx = tid + i * 256;
                Bs[buf][idx & 15][idx >> 4] = f2tf32(rb[i]);
            }
        } else {
#pragma unroll
            for (int i = 0; i < 8; i++) {
                int idx = tid + i * 256;
                Bs[buf][idx >> 7][idx & 127] = f2tf32(rb[i]);
            }
        }
    };

    load_regs(0);
    store_smem(0);
    __syncthreads();

    int cur = 0;
    for (int k0 = 0; k0 < K; k0 += BKT) {
        bool nxt = (k0 + BKT) < K;
        if (nxt) load_regs(k0 + BKT);

#pragma unroll
        for (int ks = 0; ks < BKT; ks += 8) {
            uint32_t af[4][4], bf2[4][2];
#pragma unroll
            for (int mi = 0; mi < 4; mi++) {
                int mr = wm0 + mi * 16 + gid;
                af[mi][0] = As[cur][ks + tig][mr];
                af[mi][1] = As[cur][ks + tig][mr + 8];
                af[mi][2] = As[cur][ks + tig + 4][mr];
                af[mi][3] = As[cur][ks + tig + 4][mr + 8];
            }
#pragma unroll
            for (int ni = 0; ni < 4; ni++) {
                int nc = wn0 + ni * 8 + gid;
                bf2[ni][0] = Bs[cur][ks + tig][nc];
                bf2[ni][1] = Bs[cur][ks + tig + 4][nc];
            }
#pragma unroll
            for (int mi = 0; mi < 4; mi++)
#pragma unroll
                for (int ni = 0; ni < 4; ni++)
                    mma_tf32(acc[mi][ni], af[mi], bf2[ni]);
        }

        if (nxt) store_smem(cur ^ 1);
        __syncthreads();
        cur ^= 1;
    }
}

__global__ __launch_bounds__(256, 2) void gemm2(GArgs g) {
    __shared__ uint32_t As[2][BKT][BM + PAD];
    __shared__ uint32_t Bs[2][BKT][BN + PAD];

    int bz = blockIdx.z;
    int cz = bz / g.nb, bb = bz % g.nb;
    int tid = threadIdx.x;
    int warp = tid >> 5, lane = tid & 31;
    int m0 = blockIdx.y * BM;

    const float* Ap = g.A1 + cz * g.a1c + bb * g.a1b;
    const float* Bp;
    float* Cp;
    const float* bias;
    long cs_m;
    int n0;
    if (g.multi) {
        int sx = blockIdx.x;
        Bp = g.Bm[sx]; bias = g.biasm[sx]; Cp = g.Cm[sx];
        n0 = g.noff[sx]; cs_m = g.csm[sx];
    } else {
        Bp = g.B1 + cz * g.b1c + bb * g.b1b;
        Cp = g.C + cz * g.cc + bb * g.cb;
        bias = g.bias; n0 = blockIdx.x * BN; cs_m = g.cm;
    }

    float acc[4][4][4];
#pragma unroll
    for (int i = 0; i < 4; i++)
#pragma unroll
        for (int j = 0; j < 4; j++)
#pragma unroll
            for (int f = 0; f < 4; f++) acc[i][j][f] = 0.f;

    run_pipe(Ap, g.a1m, g.a1k, Bp, g.b1k, g.b1n, g.K1,
             m0, n0, tid, warp, lane, acc, As, Bs);

    if (g.A2) {
        const float* Ap2 = g.A2 + cz * g.a2c + bb * g.a2b;
        const float* Bp2 = g.B2 + cz * g.b2c + bb * g.b2b;
        run_pipe(Ap2, g.a2m, g.a2k, Bp2, g.b2k, g.b2n, g.K2,
                 m0, n0, tid, warp, lane, acc, As, Bs);
    }

    int wm0 = (warp & 1) * 64;
    int wn0 = (warp >> 1) * 32;
    int gid = lane >> 2, tig = lane & 3;
#pragma unroll
    for (int mi = 0; mi < 4; mi++) {
        int r0 = m0 + wm0 + mi * 16 + gid;
#pragma unroll
        for (int ni = 0; ni < 4; ni++) {
            int c0 = n0 + wn0 + ni * 8 + 2 * tig;
#pragma unroll
            for (int f = 0; f < 4; f++) {
                int row = r0 + (f >> 1) * 8;
                int col = c0 + (f & 1);
                float v = acc[mi][ni][f];
                if (bias) v += bias[col];
                if (g.causal && col > row) v = 0.f;
                Cp[(long)row * cs_m + col] = v;
            }
        }
    }
}

// ---------------- decay prep ----------------
__global__ void prep_kernel() {
    int c = blockIdx.x, b = blockIdx.y, n = threadIdx.x;
    float cp = 1.f;
    long base_o = (((long)c * B_DIM + b) * CHK) * DK + n;
    for (int t = 0; t < CHK; t++) {
        long row = (long)(c * CHK + t) * B_DIM + b;
        float av = g_a[row * DK + n];
        float sg = 1.f / (1.f + expf(-av));
        cp *= fmaxf(sg, EPSV);
        g_qt[base_o + (long)t * DK] = g_q[row * DK + n] * cp;
        g_kt[base_o + (long)t * DK] = g_k[row * DK + n] / (cp + EPSV);
    }
    g_cpl[((long)c * B_DIM + b) * DK + n] = cp;
}

// ---------------- 16-step inter-chunk state scan ----------------
__global__ void scan_kernel() {
    int id = blockIdx.x * blockDim.x + threadIdx.x;
    int n = id & (DK - 1);
    int d = (id >> 7) & (DV - 1);
    int b = id >> 16;
    float s = 0.f;
#pragma unroll
    for (int c = 0; c < NCH; c++) {
        long off = (((long)c * B_DIM + b) * DV + d) * DK + n;
        g_S[off] = s;
        float cl = g_cpl[((long)c * B_DIM + b) * DK + n];
        s = cl * (s + g_U[off]);
    }
}

// ---------------- host launcher ----------------
extern "C" void kernel_launch(void* const* d_in, const int* in_sizes, int n_in,
                              void* d_out, int out_size) {
    const float* x  = (const float*)d_in[0];
    const float* Wv = (const float*)d_in[1];
    const float* bv = (const float*)d_in[2];
    const float* Wk = (const float*)d_in[3];
    const float* bk = (const float*)d_in[4];
    const float* Wq = (const float*)d_in[5];
    const float* bq = (const float*)d_in[6];
    const float* Wa = (const float*)d_in[7];
    const float* ba = (const float*)d_in[8];
    float* y = (float*)d_out;

    float *pv, *pk, *pq, *pa, *pqt, *pkt, *pA, *pU, *pS;
    cudaGetSymbolAddress((void**)&pv,  g_v);
    cudaGetSymbolAddress((void**)&pk,  g_k);
    cudaGetSymbolAddress((void**)&pq,  g_q);
    cudaGetSymbolAddress((void**)&pa,  g_a);
    cudaGetSymbolAddress((void**)&pqt, g_qt);
    cudaGetSymbolAddress((void**)&pkt, g_kt);
    cudaGetSymbolAddress((void**)&pA,  g_Am);
    cudaGetSymbolAddress((void**)&pU,  g_U);
    cudaGetSymbolAddress((void**)&pS,  g_S);
    (void)in_sizes; (void)n_in; (void)out_size;

    // ---- all four projections in ONE launch ----
    GArgs gp = {};
    gp.A1 = x; gp.a1m = IN_D; gp.a1k = 1; gp.a1c = 0; gp.a1b = 0;
    gp.b1k = 1; gp.b1n = IN_D; gp.b1c = 0; gp.b1b = 0;
    gp.K1 = IN_D; gp.A2 = 0;
    gp.nb = 1; gp.causal = 0; gp.multi = 1;
    const float* Bm[7]    = {Wv, Wv, Wv, Wv, Wk, Wq, Wa};
    const float* biasm[7] = {bv, bv, bv, bv, bk, bq, ba};
    float*       Cm[7]    = {pv, pv, pv, pv, pk, pq, pa};
    int          noff[7]  = {0, 128, 256, 384, 0, 0, 0};
    long         csm[7]   = {DV, DV, DV, DV, DK, DK, DK};
    for (int i = 0; i < 7; i++) {
        gp.Bm[i] = Bm[i]; gp.biasm[i] = biasm[i]; gp.Cm[i] = Cm[i];
        gp.noff[i] = noff[i]; gp.csm[i] = csm[i];
    }
    gemm2<<<dim3(7, T_DIM * B_DIM / BM, 1), 256>>>(gp);

    // ---- decay prep ----
    prep_kernel<<<dim3(NCH, B_DIM), DK>>>();

    // ---- A = q~ @ k~^T (causal) ----
    GArgs g3 = {};
    g3.A1 = pqt; g3.a1m = DK; g3.a1k = 1;
    g3.a1c = (long)B_DIM*CHK*DK; g3.a1b = (long)CHK*DK;
    g3.B1 = pkt; g3.b1k = 1; g3.b1n = DK;
    g3.b1c = (long)B_DIM*CHK*DK; g3.b1b = (long)CHK*DK;
    g3.C = pA; g3.cm = CHK; g3.cc = (long)B_DIM*CHK*CHK; g3.cb = (long)CHK*CHK;
    g3.K1 = DK; g3.A2 = 0; g3.nb = B_DIM; g3.causal = 1; g3.multi = 0; g3.bias = 0;
    gemm2<<<dim3(1, 1, NCH * B_DIM), 256>>>(g3);

    // ---- U = V^T @ k~ ----
    GArgs g5 = {};
    g5.A1 = pv; g5.a1m = 1; g5.a1k = (long)B_DIM*DV;
    g5.a1c = (long)CHK*B_DIM*DV; g5.a1b = DV;
    g5.B1 = pkt; g5.b1k = DK; g5.b1n = 1;
    g5.b1c = (long)B_DIM*CHK*DK; g5.b1b = (long)CHK*DK;
    g5.C = pU; g5.cm = DK; g5.cc = (long)B_DIM*DV*DK; g5.cb = (long)DV*DK;
    g5.K1 = CHK; g5.A2 = 0; g5.nb = B_DIM; g5.causal = 0; g5.multi = 0; g5.bias = 0;
    gemm2<<<dim3(1, DV / BM, NCH * B_DIM), 256>>>(g5);

    // ---- inter-chunk state scan ----
    scan_kernel<<<(B_DIM * DV * DK) / 256, 256>>>();

    // ---- y = A@V + q~@S^T (fused two-phase) ----
    GArgs gy = {};
    gy.A1 = pA; gy.a1m = CHK; gy.a1k = 1;
    gy.a1c = (long)B_DIM*CHK*CHK; gy.a1b = (long)CHK*CHK;
    gy.B1 = pv; gy.b1k = (long)B_DIM*DV; gy.b1n = 1;
    gy.b1c = (long)CHK*B_DIM*DV; gy.b1b = DV;
    gy.K1 = CHK;
    gy.A2 = pqt; gy.a2m = DK; gy.a2k = 1;
    gy.a2c = (long)B_DIM*CHK*DK; gy.a2b = (long)CHK*DK;
    gy.B2 = pS; gy.b2k = 1; gy.b2n = DK;
    gy.b2c = (long)B_DIM*DV*DK; gy.b2b = (long)DV*DK;
    gy.K2 = DK;
    gy.C = y; gy.cm = (long)B_DIM*DV; gy.cc = (long)CHK*B_DIM*DV; gy.cb = DV;
    gy.nb = B_DIM; gy.causal = 0; gy.multi = 0; gy.bias = 0;
    gemm2<<<dim3(DV / BN, 1, NCH * B_DIM), 256>>>(gy);
}

// round 4
// speedup vs baseline: 2.9037x; 1.1449x over previous
#include <cuda_runtime.h>
#include <math.h>
#include <stdint.h>

#define T_DIM  2048
#define B_DIM  8
#define IN_D   512
#define DV     512
#define DK     128
#define CHK    128
#define NCH    16
#define EPSV   1e-8f

#define BM  128
#define BN  128
#define BKT 16
#define PAD 4

// ---------------- scratch ----------------
__device__ uint32_t g_xt [T_DIM*B_DIM*IN_D];          // x as tf32
__device__ uint32_t g_wt [(DV + 3*DK) * IN_D];        // Wv|Wk|Wq|Wa as tf32
__device__ uint32_t g_v  [T_DIM*B_DIM*DV];            // v as tf32
__device__ float    g_k  [T_DIM*B_DIM*DK];
__device__ float    g_q  [T_DIM*B_DIM*DK];
__device__ float    g_a  [T_DIM*B_DIM*DK];
__device__ uint32_t g_qt [NCH*B_DIM*CHK*DK];          // tf32
__device__ uint32_t g_kt [NCH*B_DIM*CHK*DK];          // tf32
__device__ float    g_cpl[NCH*B_DIM*DK];
__device__ uint32_t g_Am [NCH*B_DIM*CHK*CHK];         // tf32
__device__ float    g_U  [NCH*B_DIM*DV*DK];
__device__ uint32_t g_S  [NCH*B_DIM*DV*DK];           // tf32

__device__ __forceinline__ uint32_t f2tf32(float f) {
    uint32_t u;
    asm("cvt.rna.tf32.f32 %0, %1;" : "=r"(u) : "f"(f));
    return u;
}

__device__ __forceinline__ void mma_tf32(float* d, const uint32_t* a, const uint32_t* b) {
    asm volatile(
        "mma.sync.aligned.m16n8k8.row.col.f32.tf32.tf32.f32 "
        "{%0,%1,%2,%3}, {%4,%5,%6,%7}, {%8,%9}, {%0,%1,%2,%3};"
        : "+f"(d[0]), "+f"(d[1]), "+f"(d[2]), "+f"(d[3])
        : "r"(a[0]), "r"(a[1]), "r"(a[2]), "r"(a[3]),
          "r"(b[0]), "r"(b[1]));
}

// ---------------- compile-time-stride tf32 double-buffered pipeline ----------------
template<long ASM, long ASK, long BSK, long BSN, int KK>
__device__ __forceinline__ void pipe(
    const uint32_t* __restrict__ Ap, const uint32_t* __restrict__ Bp,
    int m0, int n0, int tid, float acc[4][4][4],
    uint32_t (&As)[2][BKT][BM + PAD], uint32_t (&Bs)[2][BKT][BN + PAD])
{
    int warp = tid >> 5, lane = tid & 31;
    int wm0 = (warp & 1) * 64;
    int wn0 = (warp >> 1) * 32;
    int gid = lane >> 2, tig = lane & 3;

    uint4 ra[2], rb[2];

    auto loadA = [&](int k0) {
#pragma unroll
        for (int i = 0; i < 2; i++) {
            int q = tid + i * 256;
            if (ASK == 1) {
                int m = q >> 2, kq = (q & 3) * 4;
                ra[i] = *reinterpret_cast<const uint4*>(Ap + (long)(m0 + m) * ASM + (k0 + kq));
            } else {
                int k = q >> 5, m4 = (q & 31) * 4;
                ra[i] = *reinterpret_cast<const uint4*>(Ap + (long)(m0 + m4) * ASM + (long)(k0 + k) * ASK);
            }
        }
    };
    auto loadB = [&](int k0) {
#pragma unroll
        for (int i = 0; i < 2; i++) {
            int q = tid + i * 256;
            if (BSK == 1) {
                int n = q >> 2, kq = (q & 3) * 4;
                rb[i] = *reinterpret_cast<const uint4*>(Bp + (long)(n0 + n) * BSN + (k0 + kq));
            } else {
                int k = q >> 5, n4 = (q & 31) * 4;
                rb[i] = *reinterpret_cast<const uint4*>(Bp + (long)(k0 + k) * BSK + (long)(n0 + n4) * BSN);
            }
        }
    };
    auto storeA = [&](int buf) {
#pragma unroll
        for (int i = 0; i < 2; i++) {
            int q = tid + i * 256;
            if (ASK == 1) {
                int m = q >> 2, kq = (q & 3) * 4;
                const uint32_t* rr = reinterpret_cast<const uint32_t*>(&ra[i]);
#pragma unroll
                for (int j = 0; j < 4; j++) As[buf][kq + j][m] = rr[j];
            } else {
                int k = q >> 5, m4 = (q & 31) * 4;
                *reinterpret_cast<uint4*>(&As[buf][k][m4]) = ra[i];
            }
        }
    };
    auto storeB = [&](int buf) {
#pragma unroll
        for (int i = 0; i < 2; i++) {
            int q = tid + i * 256;
            if (BSK == 1) {
                int n = q >> 2, kq = (q & 3) * 4;
                const uint32_t* rr = reinterpret_cast<const uint32_t*>(&rb[i]);
#pragma unroll
                for (int j = 0; j < 4; j++) Bs[buf][kq + j][n] = rr[j];
            } else {
                int k = q >> 5, n4 = (q & 31) * 4;
                *reinterpret_cast<uint4*>(&Bs[buf][k][n4]) = rb[i];
            }
        }
    };

    loadA(0); loadB(0);
    storeA(0); storeB(0);
    __syncthreads();

    int cur = 0;
#pragma unroll 2
    for (int k0 = 0; k0 < KK; k0 += BKT) {
        bool nxt = (k0 + BKT) < KK;
        if (nxt) { loadA(k0 + BKT); loadB(k0 + BKT); }

#pragma unroll
        for (int ks = 0; ks < BKT; ks += 8) {
            uint32_t af[4][4], bf2[4][2];
#pragma unroll
            for (int mi = 0; mi < 4; mi++) {
                int mr = wm0 + mi * 16 + gid;
                af[mi][0] = As[cur][ks + tig][mr];
                af[mi][1] = As[cur][ks + tig][mr + 8];
                af[mi][2] = As[cur][ks + tig + 4][mr];
                af[mi][3] = As[cur][ks + tig + 4][mr + 8];
            }
#pragma unroll
            for (int ni = 0; ni < 4; ni++) {
                int nc = wn0 + ni * 8 + gid;
                bf2[ni][0] = Bs[cur][ks + tig][nc];
                bf2[ni][1] = Bs[cur][ks + tig + 4][nc];
            }
#pragma unroll
            for (int mi = 0; mi < 4; mi++)
#pragma unroll
                for (int ni = 0; ni < 4; ni++)
                    mma_tf32(acc[mi][ni], af[mi], bf2[ni]);
        }

        if (nxt) { storeA(cur ^ 1); storeB(cur ^ 1); }
        __syncthreads();
        cur ^= 1;
    }
}

// ---------------- generic batched GEMM (all strides compile-time) ----------------
template<long ASM, long ASK, long ACS, long ABS,
         long BSK, long BSN, long BCS, long BBS,
         long CSM, long CCS, long CBS,
         int KK, int NB, bool CAUSAL, bool OUT_TF32, bool FUSE2,
         long A2SM, long A2SK, long A2C, long A2B,
         long B2SK, long B2SN, long B2C, long B2B, int KK2>
__global__ __launch_bounds__(256, 2) void gemm_t(
    const uint32_t* __restrict__ A1, const uint32_t* __restrict__ B1, void* __restrict__ C,
    const uint32_t* __restrict__ A2, const uint32_t* __restrict__ B2)
{
    __shared__ __align__(16) uint32_t As[2][BKT][BM + PAD];
    __shared__ __align__(16) uint32_t Bs[2][BKT][BN + PAD];

    int bz = blockIdx.z;
    int cz = bz / NB, bb = bz % NB;
    int m0 = blockIdx.y * BM, n0 = blockIdx.x * BN;
    int tid = threadIdx.x;

    float acc[4][4][4];
#pragma unroll
    for (int i = 0; i < 4; i++)
#pragma unroll
        for (int j = 0; j < 4; j++)
#pragma unroll
            for (int f = 0; f < 4; f++) acc[i][j][f] = 0.f;

    pipe<ASM, ASK, BSK, BSN, KK>(A1 + cz * ACS + bb * ABS,
                                 B1 + cz * BCS + bb * BBS,
                                 m0, n0, tid, acc, As, Bs);
    if (FUSE2)
        pipe<A2SM, A2SK, B2SK, B2SN, KK2>(A2 + cz * A2C + bb * A2B,
                                          B2 + cz * B2C + bb * B2B,
                                          m0, n0, tid, acc, As, Bs);

    int warp = tid >> 5, lane = tid & 31;
    int wm0 = (warp & 1) * 64, wn0 = (warp >> 1) * 32;
    int gid = lane >> 2, tig = lane & 3;
    float*    Cf = (float*)C + cz * CCS + bb * CBS;
    uint32_t* Cu = (uint32_t*)C + cz * CCS + bb * CBS;
#pragma unroll
    for (int mi = 0; mi < 4; mi++) {
        int r0 = m0 + wm0 + mi * 16 + gid;
#pragma unroll
        for (int ni = 0; ni < 4; ni++) {
            int c0 = n0 + wn0 + ni * 8 + 2 * tig;
#pragma unroll
            for (int f = 0; f < 4; f++) {
                int row = r0 + (f >> 1) * 8;
                int col = c0 + (f & 1);
                float v = acc[mi][ni][f];
                if (CAUSAL && col > row) v = 0.f;
                long idx = (long)row * CSM + col;
                if (OUT_TF32) Cu[idx] = f2tf32(v);
                else          Cf[idx] = v;
            }
        }
    }
}

// ---------------- projection kernel (multi-output) ----------------
struct ProjArgs {
    const uint32_t* A;
    const uint32_t* Bm[7];
    const float* biasm[7];
    void* Cm[7];
    int noff[7]; int cs[7]; int otf[7];
};

__global__ __launch_bounds__(256, 2) void proj_kernel(ProjArgs g) {
    __shared__ __align__(16) uint32_t As[2][BKT][BM + PAD];
    __shared__ __align__(16) uint32_t Bs[2][BKT][BN + PAD];

    int sx = blockIdx.x;
    int m0 = blockIdx.y * BM;
    int n0 = g.noff[sx];
    int tid = threadIdx.x;

    float acc[4][4][4];
#pragma unroll
    for (int i = 0; i < 4; i++)
#pragma unroll
        for (int j = 0; j < 4; j++)
#pragma unroll
            for (int f = 0; f < 4; f++) acc[i][j][f] = 0.f;

    pipe<IN_D, 1, 1, IN_D, IN_D>(g.A, g.Bm[sx], m0, n0, tid, acc, As, Bs);

    int warp = tid >> 5, lane = tid & 31;
    int wm0 = (warp & 1) * 64, wn0 = (warp >> 1) * 32;
    int gid = lane >> 2, tig = lane & 3;
    const float* bias = g.biasm[sx];
    int cs = g.cs[sx];
    int otf = g.otf[sx];
#pragma unroll
    for (int mi = 0; mi < 4; mi++) {
        int r0 = m0 + wm0 + mi * 16 + gid;
#pragma unroll
        for (int ni = 0; ni < 4; ni++) {
            int c0 = n0 + wn0 + ni * 8 + 2 * tig;
#pragma unroll
            for (int f = 0; f < 4; f++) {
                int row = r0 + (f >> 1) * 8;
                int col = c0 + (f & 1);
                float v = acc[mi][ni][f] + bias[col];
                long idx = (long)row * cs + col;
                if (otf) ((uint32_t*)g.Cm[sx])[idx] = f2tf32(v);
                else     ((float*)g.Cm[sx])[idx]    = v;
            }
        }
    }
}

// ---------------- fp32 -> tf32 conversion pass ----------------
#define NX4   (T_DIM*B_DIM*IN_D/4)     // 2097152
#define NWV4  (DV*IN_D/4)              // 65536
#define NWK4  (DK*IN_D/4)              // 16384
__global__ void conv_all(const float4* __restrict__ x,
                         const float4* __restrict__ wv, const float4* __restrict__ wk,
                         const float4* __restrict__ wq, const float4* __restrict__ wa)
{
    long i = (long)blockIdx.x * blockDim.x + threadIdx.x;
    float4 s; uint4* dst;
    if (i < NX4) { s = x[i]; dst = (uint4*)g_xt + i; }
    else {
        long j = i - NX4;
        if (j < NWV4) { s = wv[j]; dst = (uint4*)g_wt + j; }
        else {
            j -= NWV4;
            if (j < NWK4) { s = wk[j]; dst = (uint4*)g_wt + NWV4 + j; }
            else {
                j -= NWK4;
                if (j < NWK4) { s = wq[j]; dst = (uint4*)g_wt + NWV4 + NWK4 + j; }
                else          { s = wa[j - NWK4]; dst = (uint4*)g_wt + NWV4 + 2*NWK4 + (j - NWK4); }
            }
        }
    }
    uint4 o;
    o.x = f2tf32(s.x); o.y = f2tf32(s.y); o.z = f2tf32(s.z); o.w = f2tf32(s.w);
    *dst = o;
}

// ---------------- decay prep ----------------
__global__ void prep_kernel() {
    int c = blockIdx.x, b = blockIdx.y, n = threadIdx.x;
    float cp = 1.f;
    long base_o = (((long)c * B_DIM + b) * CHK) * DK + n;
    for (int t = 0; t < CHK; t++) {
        long row = (long)(c * CHK + t) * B_DIM + b;
        float av = g_a[row * DK + n];
        float sg = 1.f / (1.f + expf(-av));
        cp *= fmaxf(sg, EPSV);
        g_qt[base_o + (long)t * DK] = f2tf32(g_q[row * DK + n] * cp);
        g_kt[base_o + (long)t * DK] = f2tf32(g_k[row * DK + n] / (cp + EPSV));
    }
    g_cpl[((long)c * B_DIM + b) * DK + n] = cp;
}

// ---------------- inter-chunk state scan ----------------
__global__ void scan_kernel() {
    int id = blockIdx.x * blockDim.x + threadIdx.x;
    int n = id & (DK - 1);
    int d = (id >> 7) & (DV - 1);
    int b = id >> 16;
    float s = 0.f;
#pragma unroll
    for (int c = 0; c < NCH; c++) {
        long off = (((long)c * B_DIM + b) * DV + d) * DK + n;
        g_S[off] = f2tf32(s);
        float cl = g_cpl[((long)c * B_DIM + b) * DK + n];
        s = cl * (s + g_U[off]);
    }
}

// ---------------- host launcher ----------------
extern "C" void kernel_launch(void* const* d_in, const int* in_sizes, int n_in,
                              void* d_out, int out_size) {
    const float* x  = (const float*)d_in[0];
    const float* Wv = (const float*)d_in[1];
    const float* bv = (const float*)d_in[2];
    const float* Wk = (const float*)d_in[3];
    const float* bk = (const float*)d_in[4];
    const float* Wq = (const float*)d_in[5];
    const float* bq = (const float*)d_in[6];
    const float* Wa = (const float*)d_in[7];
    const float* ba = (const float*)d_in[8];
    float* y = (float*)d_out;
    (void)in_sizes; (void)n_in; (void)out_size;

    uint32_t *pxt, *pwt, *pv, *pqt, *pkt, *pA, *pS;
    float *pk, *pq, *pa, *pU;
    cudaGetSymbolAddress((void**)&pxt, g_xt);
    cudaGetSymbolAddress((void**)&pwt, g_wt);
    cudaGetSymbolAddress((void**)&pv,  g_v);
    cudaGetSymbolAddress((void**)&pk,  g_k);
    cudaGetSymbolAddress((void**)&pq,  g_q);
    cudaGetSymbolAddress((void**)&pa,  g_a);
    cudaGetSymbolAddress((void**)&pqt, g_qt);
    cudaGetSymbolAddress((void**)&pkt, g_kt);
    cudaGetSymbolAddress((void**)&pA,  g_Am);
    cudaGetSymbolAddress((void**)&pU,  g_U);
    cudaGetSymbolAddress((void**)&pS,  g_S);

    // ---- tf32 conversion pass ----
    {
        long tot4 = NX4 + NWV4 + 3 * (long)NWK4;
        conv_all<<<(unsigned)((tot4 + 255) / 256), 256>>>(
            (const float4*)x, (const float4*)Wv, (const float4*)Wk,
            (const float4*)Wq, (const float4*)Wa);
    }

    // ---- projections (one launch) ----
    {
        ProjArgs gp;
        gp.A = pxt;
        const uint32_t* wv_t = pwt;
        const uint32_t* wk_t = pwt + NWV4 * 4;
        const uint32_t* wq_t = pwt + (NWV4 + NWK4) * 4;
        const uint32_t* wa_t = pwt + (NWV4 + 2 * NWK4) * 4;
        const uint32_t* Bm[7]    = {wv_t, wv_t, wv_t, wv_t, wk_t, wq_t, wa_t};
        const float*    biasm[7] = {bv, bv, bv, bv, bk, bq, ba};
        void*           Cm[7]    = {pv, pv, pv, pv, pk, pq, pa};
        int             noff[7]  = {0, 128, 256, 384, 0, 0, 0};
        int             cs[7]    = {DV, DV, DV, DV, DK, DK, DK};
        int             otf[7]   = {1, 1, 1, 1, 0, 0, 0};
        for (int i = 0; i < 7; i++) {
            gp.Bm[i] = Bm[i]; gp.biasm[i] = biasm[i]; gp.Cm[i] = Cm[i];
            gp.noff[i] = noff[i]; gp.cs[i] = cs[i]; gp.otf[i] = otf[i];
        }
        proj_kernel<<<dim3(7, T_DIM * B_DIM / BM, 1), 256>>>(gp);
    }

    // ---- decay prep ----
    prep_kernel<<<dim3(NCH, B_DIM), DK>>>();

    // ---- A = q~ @ k~^T (causal, tf32 out) ----
    gemm_t<DK, 1, (long)B_DIM*CHK*DK, (long)CHK*DK,
           1, DK, (long)B_DIM*CHK*DK, (long)CHK*DK,
           CHK, (long)B_DIM*CHK*CHK, (long)CHK*CHK,
           DK, B_DIM, true, true, false,
           0,0,0,0, 0,0,0,0, 0>
        <<<dim3(1, 1, NCH * B_DIM), 256>>>(pqt, pkt, pA, 0, 0);

    // ---- U = V^T @ k~ (fp32 out) ----
    gemm_t<1, (long)B_DIM*DV, (long)CHK*B_DIM*DV, DV,
           DK, 1, (long)B_DIM*CHK*DK, (long)CHK*DK,
           DK, (long)B_DIM*DV*DK, (long)DV*DK,
           CHK, B_DIM, false, false, false,
           0,0,0,0, 0,0,0,0, 0>
        <<<dim3(1, DV / BM, NCH * B_DIM), 256>>>(pv, pkt, pU, 0, 0);

    // ---- inter-chunk state scan ----
    scan_kernel<<<(B_DIM * DV * DK) / 256, 256>>>();

    // ---- y = A@V + q~@S^T ----
    gemm_t<CHK, 1, (long)B_DIM*CHK*CHK, (long)CHK*CHK,
           (long)B_DIM*DV, 1, (long)CHK*B_DIM*DV, DV,
           (long)B_DIM*DV, (long)CHK*B_DIM*DV, DV,
           CHK, B_DIM, false, false, true,
           DK, 1, (long)B_DIM*CHK*DK, (long)CHK*DK,
           1, DK, (long)B_DIM*DV*DK, (long)DV*DK, DK>
        <<<dim3(DV / BN, 1, NCH * B_DIM), 256>>>(pA, pv, y, pqt, pS);
}

// round 5
// speedup vs baseline: 3.3283x; 1.1462x over previous
#include <cuda_runtime.h>
#include <math.h>
#include <stdint.h>

#define T_DIM  2048
#define B_DIM  8
#define IN_D   512
#define DV     512
#define DK     128
#define CHK    128
#define NCH    16
#define EPSV   1e-8f

#define BM  128
#define BN  128
#define BKT 16
#define PAD 4
#define NSTG 3
#define SZ   2560                       // words per stage per operand (max of both layouts)
#define DYN_SMEM (NSTG * SZ * 2 * 4)    // 61440 bytes

// ---------------- scratch ----------------
__device__ uint32_t g_xt [T_DIM*B_DIM*IN_D];
__device__ uint32_t g_wt [(DV + 3*DK) * IN_D];
__device__ uint32_t g_v  [T_DIM*B_DIM*DV];
__device__ float    g_k  [T_DIM*B_DIM*DK];
__device__ float    g_q  [T_DIM*B_DIM*DK];
__device__ float    g_a  [T_DIM*B_DIM*DK];
__device__ uint32_t g_qt [NCH*B_DIM*CHK*DK];
__device__ uint32_t g_kt [NCH*B_DIM*CHK*DK];
__device__ float    g_cpl[NCH*B_DIM*DK];
__device__ uint32_t g_Am [NCH*B_DIM*CHK*CHK];
__device__ float    g_U  [NCH*B_DIM*DV*DK];
__device__ uint32_t g_S  [NCH*B_DIM*DV*DK];

__device__ __forceinline__ uint32_t f2tf32(float f) {
    uint32_t u;
    asm("cvt.rna.tf32.f32 %0, %1;" : "=r"(u) : "f"(f));
    return u;
}

__device__ __forceinline__ void mma_tf32(float* d, const uint32_t* a, const uint32_t* b) {
    asm volatile(
        "mma.sync.aligned.m16n8k8.row.col.f32.tf32.tf32.f32 "
        "{%0,%1,%2,%3}, {%4,%5,%6,%7}, {%8,%9}, {%0,%1,%2,%3};"
        : "+f"(d[0]), "+f"(d[1]), "+f"(d[2]), "+f"(d[3])
        : "r"(a[0]), "r"(a[1]), "r"(a[2]), "r"(a[3]),
          "r"(b[0]), "r"(b[1]));
}

__device__ __forceinline__ void cp16(uint32_t* smem, const uint32_t* g) {
    uint32_t s = (uint32_t)__cvta_generic_to_shared(smem);
    asm volatile("cp.async.cg.shared.global [%0], [%1], 16;" :: "r"(s), "l"(g));
}
__device__ __forceinline__ void cp_commit() {
    asm volatile("cp.async.commit_group;");
}
__device__ __forceinline__ void cp_wait1() {
    asm volatile("cp.async.wait_group 1;");
}

// ---------------- 3-stage cp.async tf32 pipeline ----------------
// AKC (k-stride==1): smem layout [row][k], row stride BKT+PAD (conflict-free frag reads)
// else (row-stride==1): smem layout [k][row], row stride BM/BN+PAD
template<long ASM, long ASK, long BSK, long BSN, int KK>
__device__ __forceinline__ void pipe(
    const uint32_t* __restrict__ Ap, const uint32_t* __restrict__ Bp,
    int m0, int n0, int tid, float acc[4][4][4],
    uint32_t* SA, uint32_t* SB)
{
    constexpr bool AKC = (ASK == 1);
    constexpr bool BKC = (BSK == 1);
    constexpr int NKI = KK / BKT;

    int warp = tid >> 5, lane = tid & 31;
    int wm0 = (warp & 1) * 64;
    int wn0 = (warp >> 1) * 32;
    int gid = lane >> 2, tig = lane & 3;

    auto issueA = [&](uint32_t* dst, int k0) {
#pragma unroll
        for (int i = 0; i < 2; i++) {
            int q = tid + i * 256;
            if (AKC) {
                int m = q >> 2, kq = (q & 3) << 2;
                cp16(dst + m * (BKT + PAD) + kq,
                     Ap + (long)(m0 + m) * ASM + (k0 + kq));
            } else {
                int k = q >> 5, m4 = (q & 31) << 2;
                cp16(dst + k * (BM + PAD) + m4,
                     Ap + (long)(m0 + m4) * ASM + (long)(k0 + k) * ASK);
            }
        }
    };
    auto issueB = [&](uint32_t* dst, int k0) {
#pragma unroll
        for (int i = 0; i < 2; i++) {
            int q = tid + i * 256;
            if (BKC) {
                int n = q >> 2, kq = (q & 3) << 2;
                cp16(dst + n * (BKT + PAD) + kq,
                     Bp + (long)(n0 + n) * BSN + (k0 + kq));
            } else {
                int k = q >> 5, n4 = (q & 31) << 2;
                cp16(dst + k * (BN + PAD) + n4,
                     Bp + (long)(k0 + k) * BSK + (long)(n0 + n4) * BSN);
            }
        }
    };

    __syncthreads();   // protect stage buffers from previous use

    issueA(SA, 0); issueB(SB, 0); cp_commit();
    if (NKI > 1) { issueA(SA + SZ, BKT); issueB(SB + SZ, BKT); }
    cp_commit();

    int stage = 0;
    for (int i = 0; i < NKI; i++) {
        cp_wait1();
        __syncthreads();
        {
            int s2 = stage + 2; if (s2 >= NSTG) s2 -= NSTG;
            if (i + 2 < NKI) {
                issueA(SA + s2 * SZ, (i + 2) * BKT);
                issueB(SB + s2 * SZ, (i + 2) * BKT);
            }
            cp_commit();
        }
        const uint32_t* sa = SA + stage * SZ;
        const uint32_t* sb = SB + stage * SZ;
#pragma unroll
        for (int ks = 0; ks < BKT; ks += 8) {
            uint32_t af[4][4], bf2[4][2];
#pragma unroll
            for (int mi = 0; mi < 4; mi++) {
                int mr = wm0 + mi * 16 + gid;
                if (AKC) {
                    const uint32_t* r0p = sa + mr * (BKT + PAD);
                    const uint32_t* r1p = sa + (mr + 8) * (BKT + PAD);
                    af[mi][0] = r0p[ks + tig];
                    af[mi][1] = r1p[ks + tig];
                    af[mi][2] = r0p[ks + tig + 4];
                    af[mi][3] = r1p[ks + tig + 4];
                } else {
                    af[mi][0] = sa[(ks + tig) * (BM + PAD) + mr];
                    af[mi][1] = sa[(ks + tig) * (BM + PAD) + mr + 8];
                    af[mi][2] = sa[(ks + tig + 4) * (BM + PAD) + mr];
                    af[mi][3] = sa[(ks + tig + 4) * (BM + PAD) + mr + 8];
                }
            }
#pragma unroll
            for (int ni = 0; ni < 4; ni++) {
                int nc = wn0 + ni * 8 + gid;
                if (BKC) {
                    const uint32_t* rp = sb + nc * (BKT + PAD);
                    bf2[ni][0] = rp[ks + tig];
                    bf2[ni][1] = rp[ks + tig + 4];
                } else {
                    bf2[ni][0] = sb[(ks + tig) * (BN + PAD) + nc];
                    bf2[ni][1] = sb[(ks + tig + 4) * (BN + PAD) + nc];
                }
            }
#pragma unroll
            for (int mi = 0; mi < 4; mi++)
#pragma unroll
                for (int ni = 0; ni < 4; ni++)
                    mma_tf32(acc[mi][ni], af[mi], bf2[ni]);
        }
        stage++; if (stage == NSTG) stage = 0;
    }
}

// ---------------- generic batched GEMM (compile-time strides) ----------------
template<long ASM, long ASK, long ACS, long ABS,
         long BSK, long BSN, long BCS, long BBS,
         long CSM, long CCS, long CBS,
         int KK, int NB, bool CAUSAL, bool OUT_TF32, bool FUSE2,
         long A2SM, long A2SK, long A2C, long A2B,
         long B2SK, long B2SN, long B2C, long B2B, int KK2>
__global__ __launch_bounds__(256, 2) void gemm_t(
    const uint32_t* __restrict__ A1, const uint32_t* __restrict__ B1, void* __restrict__ C,
    const uint32_t* __restrict__ A2, const uint32_t* __restrict__ B2)
{
    extern __shared__ uint32_t dynsm[];
    uint32_t* SA = dynsm;
    uint32_t* SB = dynsm + NSTG * SZ;

    int bz = blockIdx.z;
    int cz = bz / NB, bb = bz % NB;
    int m0 = blockIdx.y * BM, n0 = blockIdx.x * BN;
    int tid = threadIdx.x;

    float acc[4][4][4];
#pragma unroll
    for (int i = 0; i < 4; i++)
#pragma unroll
        for (int j = 0; j < 4; j++)
#pragma unroll
            for (int f = 0; f < 4; f++) acc[i][j][f] = 0.f;

    pipe<ASM, ASK, BSK, BSN, KK>(A1 + cz * ACS + bb * ABS,
                                 B1 + cz * BCS + bb * BBS,
                                 m0, n0, tid, acc, SA, SB);
    if (FUSE2)
        pipe<A2SM, A2SK, B2SK, B2SN, KK2>(A2 + cz * A2C + bb * A2B,
                                          B2 + cz * B2C + bb * B2B,
                                          m0, n0, tid, acc, SA, SB);

    int warp = tid >> 5, lane = tid & 31;
    int wm0 = (warp & 1) * 64, wn0 = (warp >> 1) * 32;
    int gid = lane >> 2, tig = lane & 3;
    float*    Cf = (float*)C + cz * CCS + bb * CBS;
    uint32_t* Cu = (uint32_t*)C + cz * CCS + bb * CBS;
#pragma unroll
    for (int mi = 0; mi < 4; mi++) {
        int r0 = m0 + wm0 + mi * 16 + gid;
#pragma unroll
        for (int ni = 0; ni < 4; ni++) {
            int c0 = n0 + wn0 + ni * 8 + 2 * tig;
#pragma unroll
            for (int f = 0; f < 4; f++) {
                int row = r0 + (f >> 1) * 8;
                int col = c0 + (f & 1);
                float v = acc[mi][ni][f];
                if (CAUSAL && col > row) v = 0.f;
                long idx = (long)row * CSM + col;
                if (OUT_TF32) Cu[idx] = f2tf32(v);
                else          Cf[idx] = v;
            }
        }
    }
}

// ---------------- projection kernel (multi-output) ----------------
struct ProjArgs {
    const uint32_t* A;
    const uint32_t* Bm[7];
    const float* biasm[7];
    void* Cm[7];
    int noff[7]; int cs[7]; int otf[7];
};

__global__ __launch_bounds__(256, 2) void proj_kernel(ProjArgs g) {
    extern __shared__ uint32_t dynsm[];
    uint32_t* SA = dynsm;
    uint32_t* SB = dynsm + NSTG * SZ;

    int sx = blockIdx.x;
    int m0 = blockIdx.y * BM;
    int n0 = g.noff[sx];
    int tid = threadIdx.x;

    float acc[4][4][4];
#pragma unroll
    for (int i = 0; i < 4; i++)
#pragma unroll
        for (int j = 0; j < 4; j++)
#pragma unroll
            for (int f = 0; f < 4; f++) acc[i][j][f] = 0.f;

    pipe<IN_D, 1, 1, IN_D, IN_D>(g.A, g.Bm[sx], m0, n0, tid, acc, SA, SB);

    int warp = tid >> 5, lane = tid & 31;
    int wm0 = (warp & 1) * 64, wn0 = (warp >> 1) * 32;
    int gid = lane >> 2, tig = lane & 3;
    const float* bias = g.biasm[sx];
    int cs = g.cs[sx];
    int otf = g.otf[sx];
#pragma unroll
    for (int mi = 0; mi < 4; mi++) {
        int r0 = m0 + wm0 + mi * 16 + gid;
#pragma unroll
        for (int ni = 0; ni < 4; ni++) {
            int c0 = n0 + wn0 + ni * 8 + 2 * tig;
#pragma unroll
            for (int f = 0; f < 4; f++) {
                int row = r0 + (f >> 1) * 8;
                int col = c0 + (f & 1);
                float v = acc[mi][ni][f] + bias[col];
                long idx = (long)row * cs + col;
                if (otf) ((uint32_t*)g.Cm[sx])[idx] = f2tf32(v);
                else     ((float*)g.Cm[sx])[idx]    = v;
            }
        }
    }
}

// ---------------- fp32 -> tf32 conversion pass ----------------
#define NX4   (T_DIM*B_DIM*IN_D/4)
#define NWV4  (DV*IN_D/4)
#define NWK4  (DK*IN_D/4)
__global__ void conv_all(const float4* __restrict__ x,
                         const float4* __restrict__ wv, const float4* __restrict__ wk,
                         const float4* __restrict__ wq, const float4* __restrict__ wa)
{
    long i = (long)blockIdx.x * blockDim.x + threadIdx.x;
    float4 s; uint4* dst;
    if (i < NX4) { s = x[i]; dst = (uint4*)g_xt + i; }
    else {
        long j = i - NX4;
        if (j < NWV4) { s = wv[j]; dst = (uint4*)g_wt + j; }
        else {
            j -= NWV4;
            if (j < NWK4) { s = wk[j]; dst = (uint4*)g_wt + NWV4 + j; }
            else {
                j -= NWK4;
                if (j < NWK4) { s = wq[j]; dst = (uint4*)g_wt + NWV4 + NWK4 + j; }
                else          { s = wa[j - NWK4]; dst = (uint4*)g_wt + NWV4 + 2*NWK4 + (j - NWK4); }
            }
        }
    }
    uint4 o;
    o.x = f2tf32(s.x); o.y = f2tf32(s.y); o.z = f2tf32(s.z); o.w = f2tf32(s.w);
    *dst = o;
}

// ---------------- decay prep ----------------
__global__ void prep_kernel() {
    int c = blockIdx.x, b = blockIdx.y, n = threadIdx.x;
    float cp = 1.f;
    long base_o = (((long)c * B_DIM + b) * CHK) * DK + n;
    for (int t = 0; t < CHK; t++) {
        long row = (long)(c * CHK + t) * B_DIM + b;
        float av = g_a[row * DK + n];
        float sg = 1.f / (1.f + expf(-av));
        cp *= fmaxf(sg, EPSV);
        g_qt[base_o + (long)t * DK] = f2tf32(g_q[row * DK + n] * cp);
        g_kt[base_o + (long)t * DK] = f2tf32(g_k[row * DK + n] / (cp + EPSV));
    }
    g_cpl[((long)c * B_DIM + b) * DK + n] = cp;
}

// ---------------- inter-chunk state scan ----------------
__global__ void scan_kernel() {
    int id = blockIdx.x * blockDim.x + threadIdx.x;
    int n = id & (DK - 1);
    int d = (id >> 7) & (DV - 1);
    int b = id >> 16;
    float s = 0.f;
#pragma unroll
    for (int c = 0; c < NCH; c++) {
        long off = (((long)c * B_DIM + b) * DV + d) * DK + n;
        g_S[off] = f2tf32(s);
        float cl = g_cpl[((long)c * B_DIM + b) * DK + n];
        s = cl * (s + g_U[off]);
    }
}

// ---------------- host launcher ----------------
extern "C" void kernel_launch(void* const* d_in, const int* in_sizes, int n_in,
                              void* d_out, int out_size) {
    const float* x  = (const float*)d_in[0];
    const float* Wv = (const float*)d_in[1];
    const float* bv = (const float*)d_in[2];
    const float* Wk = (const float*)d_in[3];
    const float* bk = (const float*)d_in[4];
    const float* Wq = (const float*)d_in[5];
    const float* bq = (const float*)d_in[6];
    const float* Wa = (const float*)d_in[7];
    const float* ba = (const float*)d_in[8];
    float* y = (float*)d_out;
    (void)in_sizes; (void)n_in; (void)out_size;

    uint32_t *pxt, *pwt, *pv, *pqt, *pkt, *pA, *pS;
    float *pk, *pq, *pa, *pU;
    cudaGetSymbolAddress((void**)&pxt, g_xt);
    cudaGetSymbolAddress((void**)&pwt, g_wt);
    cudaGetSymbolAddress((void**)&pv,  g_v);
    cudaGetSymbolAddress((void**)&pk,  g_k);
    cudaGetSymbolAddress((void**)&pq,  g_q);
    cudaGetSymbolAddress((void**)&pa,  g_a);
    cudaGetSymbolAddress((void**)&pqt, g_qt);
    cudaGetSymbolAddress((void**)&pkt, g_kt);
    cudaGetSymbolAddress((void**)&pA,  g_Am);
    cudaGetSymbolAddress((void**)&pU,  g_U);
    cudaGetSymbolAddress((void**)&pS,  g_S);

    // kernel pointers for attribute setup
    auto kA = gemm_t<DK, 1, (long)B_DIM*CHK*DK, (long)CHK*DK,
                     1, DK, (long)B_DIM*CHK*DK, (long)CHK*DK,
                     CHK, (long)B_DIM*CHK*CHK, (long)CHK*CHK,
                     DK, B_DIM, true, true, false,
                     0,0,0,0, 0,0,0,0, 0>;
    auto kU = gemm_t<1, (long)B_DIM*DV, (long)CHK*B_DIM*DV, DV,
                     DK, 1, (long)B_DIM*CHK*DK, (long)CHK*DK,
                     DK, (long)B_DIM*DV*DK, (long)DV*DK,
                     CHK, B_DIM, false, false, false,
                     0,0,0,0, 0,0,0,0, 0>;
    auto kY = gemm_t<CHK, 1, (long)B_DIM*CHK*CHK, (long)CHK*CHK,
                     (long)B_DIM*DV, 1, (long)CHK*B_DIM*DV, DV,
                     (long)B_DIM*DV, (long)CHK*B_DIM*DV, DV,
                     CHK, B_DIM, false, false, true,
                     DK, 1, (long)B_DIM*CHK*DK, (long)CHK*DK,
                     1, DK, (long)B_DIM*DV*DK, (long)DV*DK, DK>;

    cudaFuncSetAttribute(proj_kernel, cudaFuncAttributeMaxDynamicSharedMemorySize, DYN_SMEM);
    cudaFuncSetAttribute(kA, cudaFuncAttributeMaxDynamicSharedMemorySize, DYN_SMEM);
    cudaFuncSetAttribute(kU, cudaFuncAttributeMaxDynamicSharedMemorySize, DYN_SMEM);
    cudaFuncSetAttribute(kY, cudaFuncAttributeMaxDynamicSharedMemorySize, DYN_SMEM);

    // ---- tf32 conversion pass ----
    {
        long tot4 = NX4 + NWV4 + 3 * (long)NWK4;
        conv_all<<<(unsigned)((tot4 + 255) / 256), 256>>>(
            (const float4*)x, (const float4*)Wv, (const float4*)Wk,
            (const float4*)Wq, (const float4*)Wa);
    }

    // ---- projections (one launch) ----
    {
        ProjArgs gp;
        gp.A = pxt;
        const uint32_t* wv_t = pwt;
        const uint32_t* wk_t = pwt + NWV4 * 4;
        const uint32_t* wq_t = pwt + (NWV4 + NWK4) * 4;
        const uint32_t* wa_t = pwt + (NWV4 + 2 * NWK4) * 4;
        const uint32_t* Bm[7]    = {wv_t, wv_t, wv_t, wv_t, wk_t, wq_t, wa_t};
        const float*    biasm[7] = {bv, bv, bv, bv, bk, bq, ba};
        void*           Cm[7]    = {pv, pv, pv, pv, pk, pq, pa};
        int             noff[7]  = {0, 128, 256, 384, 0, 0, 0};
        int             cs[7]    = {DV, DV, DV, DV, DK, DK, DK};
        int             otf[7]   = {1, 1, 1, 1, 0, 0, 0};
        for (int i = 0; i < 7; i++) {
            gp.Bm[i] = Bm[i]; gp.biasm[i] = biasm[i]; gp.Cm[i] = Cm[i];
            gp.noff[i] = noff[i]; gp.cs[i] = cs[i]; gp.otf[i] = otf[i];
        }
        proj_kernel<<<dim3(7, T_DIM * B_DIM / BM, 1), 256, DYN_SMEM>>>(gp);
    }

    // ---- decay prep ----
    prep_kernel<<<dim3(NCH, B_DIM), DK>>>();

    // ---- A = q~ @ k~^T (causal, tf32 out) ----
    kA<<<dim3(1, 1, NCH * B_DIM), 256, DYN_SMEM>>>(pqt, pkt, pA, 0, 0);

    // ---- U = V^T @ k~ (fp32 out) ----
    kU<<<dim3(1, DV / BM, NCH * B_DIM), 256, DYN_SMEM>>>(pv, pkt, pU, 0, 0);

    // ---- inter-chunk state scan ----
    scan_kernel<<<(B_DIM * DV * DK) / 256, 256>>>();

    // ---- y = A@V + q~@S^T ----
    kY<<<dim3(DV / BN, 1, NCH * B_DIM), 256, DYN_SMEM>>>(pA, pv, y, pqt, pS);
}